// round 4
// baseline (speedup 1.0000x reference)
#include <cuda_runtime.h>
#include <math.h>

#define NN 50000
#define HH 128
#define NHEADS 8
#define HDIM 16
#define RR 100
#define EE 800000
#define FFH 512

// ---------------- scratch (static device globals; no allocation) ----------------
__device__ float g_q[NN * HH];
__device__ float g_k[NN * HH];
__device__ float g_v[NN * HH];
__device__ float g_scores[EE * NHEADS];
__device__ float g_segmax[NN * NHEADS];
__device__ float g_denom[NN * NHEADS];
__device__ float g_agg[NN * HH];
__device__ float g_attn[NN * HH];
__device__ float g_x1[NN * HH];
__device__ float g_h1[NN * FFH];
__device__ float g_ffn[NN * HH];
__device__ float g_bq[HH];
__device__ float g_bk[HH];
__device__ float g_comb[RR * FFH];

// ---------------- zero scratch that is atomically accumulated ----------------
__global__ void zero_kernel() {
    int i = blockIdx.x * blockDim.x + threadIdx.x;
    if (i < NN * HH) g_agg[i] = 0.0f;
    if (i < NN * NHEADS) { g_segmax[i] = 0.0f; g_denom[i] = 0.0f; }
}

// ---------------- fold query embedding into effective q/k biases ----------------
__global__ void prep_bias(const float* __restrict__ qemb,
                          const float* __restrict__ Wq, const float* __restrict__ Wk,
                          const float* __restrict__ bq, const float* __restrict__ bk) {
    int t = threadIdx.x;              // 0..255
    int o = t & 127;
    const float* Wrow = (t < 128 ? Wq : Wk) + o * (2 * HH) + HH;
    float acc = (t < 128 ? bq[o] : bk[o]);
#pragma unroll 4
    for (int j = 0; j < HH; j++) acc += qemb[j] * Wrow[j];
    if (t < 128) g_bq[o] = acc; else g_bk[o] = acc;
}

// ---------------- generic GEMM: C[M,Nout] = A[M,K] @ W.T + bias (W row-major [Nout, ldw]) ----------------
template <bool GELU>
__global__ __launch_bounds__(256) void gemm_bias(
    const float* __restrict__ A, const float* __restrict__ W,
    const float* __restrict__ bias, float* __restrict__ C,
    int M, int Nout, int K, int ldw)
{
    __shared__ float As[16][132];
    __shared__ float Bs[16][132];
    int tid = threadIdx.x;
    int tx = tid & 15, ty = tid >> 4;
    int row0 = blockIdx.y * 128;
    int col0 = blockIdx.x * 128;

    float acc[8][8];
#pragma unroll
    for (int i = 0; i < 8; i++)
#pragma unroll
        for (int j = 0; j < 8; j++) acc[i][j] = 0.0f;

    for (int k0 = 0; k0 < K; k0 += 16) {
        // A tile: 128 rows x 16 k  (2 float4 per thread)
#pragma unroll
        for (int l = 0; l < 2; l++) {
            int i = tid + l * 256;          // float4 index 0..511
            int r = i >> 2;
            int kq = i & 3;
            int grow = row0 + r;
            float4 v = make_float4(0.f, 0.f, 0.f, 0.f);
            if (grow < M)
                v = *(const float4*)(A + (size_t)grow * K + k0 + kq * 4);
            As[kq * 4 + 0][r] = v.x; As[kq * 4 + 1][r] = v.y;
            As[kq * 4 + 2][r] = v.z; As[kq * 4 + 3][r] = v.w;
        }
        // B tile: Bs[k][n] = W[(col0+n)*ldw + k0+k]
#pragma unroll
        for (int l = 0; l < 2; l++) {
            int i = tid + l * 256;
            int n = i >> 2;
            int kq = i & 3;
            float4 v = *(const float4*)(W + (size_t)(col0 + n) * ldw + k0 + kq * 4);
            Bs[kq * 4 + 0][n] = v.x; Bs[kq * 4 + 1][n] = v.y;
            Bs[kq * 4 + 2][n] = v.z; Bs[kq * 4 + 3][n] = v.w;
        }
        __syncthreads();
#pragma unroll
        for (int kk = 0; kk < 16; kk++) {
            float a[8], b[8];
#pragma unroll
            for (int i = 0; i < 8; i++) a[i] = As[kk][ty * 8 + i];
#pragma unroll
            for (int j = 0; j < 8; j++) b[j] = Bs[kk][tx * 8 + j];
#pragma unroll
            for (int i = 0; i < 8; i++)
#pragma unroll
                for (int j = 0; j < 8; j++) acc[i][j] += a[i] * b[j];
        }
        __syncthreads();
    }
#pragma unroll
    for (int i = 0; i < 8; i++) {
        int grow = row0 + ty * 8 + i;
        if (grow >= M) continue;
#pragma unroll
        for (int j = 0; j < 8; j++) {
            int gcol = col0 + tx * 8 + j;
            float c = acc[i][j] + bias[gcol];
            if (GELU) c = 0.5f * c * (1.0f + erff(c * 0.70710678118654752f));
            C[(size_t)grow * Nout + gcol] = c;
        }
    }
}

// ---------------- edge pass A: scores + segment max ----------------
__global__ void edge_scores(const int* __restrict__ ei, const int* __restrict__ et,
                            const float* __restrict__ rel) {
    int idx = blockIdx.x * blockDim.x + threadIdx.x;
    if (idx >= EE * NHEADS) return;
    int e = idx >> 3, h = idx & 7;
    int s = ei[e];
    int d = ei[EE + e];
    int r = et[e];
    const float4* qp = (const float4*)(g_q + s * 0 + (size_t)d * HH + h * HDIM);
    const float4* kp = (const float4*)(g_k + (size_t)s * HH + h * HDIM);
    const float4* rp = (const float4*)(rel + (size_t)r * HH + h * HDIM);
    float acc = 0.0f;
#pragma unroll
    for (int i = 0; i < 4; i++) {
        float4 qv = qp[i], kv = kp[i], rv = rp[i];
        acc += qv.x * (kv.x + rv.x) + qv.y * (kv.y + rv.y)
             + qv.z * (kv.z + rv.z) + qv.w * (kv.w + rv.w);
    }
    float sc = acc * 0.25f;  // 1/sqrt(16)
    g_scores[idx] = sc;
    if (sc > 0.0f)
        atomicMax((int*)&g_segmax[d * NHEADS + h], __float_as_int(sc));
}

// ---------------- edge pass B: exp + weighted aggregation (unnormalized) ----------------
__global__ void edge_agg(const int* __restrict__ ei) {
    int idx = blockIdx.x * blockDim.x + threadIdx.x;
    if (idx >= EE * NHEADS) return;
    int e = idx >> 3, h = idx & 7;
    int s = ei[e];
    int d = ei[EE + e];
    float sc = g_scores[idx];
    float m = g_segmax[d * NHEADS + h];
    float ex = __expf(sc - m);
    atomicAdd(&g_denom[d * NHEADS + h], ex);
    const float4* vp = (const float4*)(g_v + (size_t)s * HH + h * HDIM);
    float* ap = g_agg + (size_t)d * HH + h * HDIM;
#pragma unroll
    for (int i = 0; i < 4; i++) {
        float4 vv = vp[i];
        asm volatile("red.global.add.v4.f32 [%0], {%1,%2,%3,%4};"
                     :: "l"(ap + i * 4),
                        "f"(ex * vv.x), "f"(ex * vv.y), "f"(ex * vv.z), "f"(ex * vv.w)
                     : "memory");
    }
}

// ---------------- normalize aggregated messages by denom ----------------
__global__ void norm_agg() {
    int i = blockIdx.x * blockDim.x + threadIdx.x;
    if (i >= NN * HH) return;
    int node = i >> 7;
    int h = (i >> 4) & 7;
    g_agg[i] = g_agg[i] / (g_denom[node * NHEADS + h] + 1e-8f);
}

// ---------------- layernorm(a + r) * g + b, warp per row ----------------
__global__ void ln_kernel(const float* __restrict__ a, const float* __restrict__ r,
                          const float* __restrict__ gam, const float* __restrict__ bet,
                          float* __restrict__ out, int M) {
    int warp = (blockIdx.x * blockDim.x + threadIdx.x) >> 5;
    int lane = threadIdx.x & 31;
    if (warp >= M) return;
    const float4* ap = (const float4*)(a + (size_t)warp * HH);
    const float4* rp = (const float4*)(r + (size_t)warp * HH);
    float4 va = ap[lane];
    float4 vr = rp[lane];
    float x0 = va.x + vr.x, x1 = va.y + vr.y, x2 = va.z + vr.z, x3 = va.w + vr.w;
    float s = x0 + x1 + x2 + x3;
    float q = x0 * x0 + x1 * x1 + x2 * x2 + x3 * x3;
#pragma unroll
    for (int off = 16; off; off >>= 1) {
        s += __shfl_xor_sync(0xffffffffu, s, off);
        q += __shfl_xor_sync(0xffffffffu, q, off);
    }
    float mu = s * (1.0f / HH);
    float var = q * (1.0f / HH) - mu * mu;
    float inv = rsqrtf(var + 1e-5f);
    float4 vg = ((const float4*)gam)[lane];
    float4 vb = ((const float4*)bet)[lane];
    float4 o;
    o.x = (x0 - mu) * inv * vg.x + vb.x;
    o.y = (x1 - mu) * inv * vg.y + vb.y;
    o.z = (x2 - mu) * inv * vg.z + vb.z;
    o.w = (x3 - mu) * inv * vg.w + vb.w;
    ((float4*)(out + (size_t)warp * HH))[lane] = o;
}

// ---------------- relational layer ----------------
__global__ void rel1(const float* __restrict__ rel, const float* __restrict__ relW,
                     const float* __restrict__ relb) {
    int idx = blockIdx.x * blockDim.x + threadIdx.x;   // < RR*FFH = 51200
    if (idx >= RR * FFH) return;
    int r = idx / FFH;
    int j = idx - r * FFH;
    int kk = j >> 7;
    int o = j & 127;
    const float4* rp = (const float4*)(rel + r * HH);
    const float4* wp = (const float4*)(relW + kk * HH * HH + o * HH);
    float acc = relb[j];
#pragma unroll 8
    for (int i = 0; i < 32; i++) {
        float4 a = rp[i], b = wp[i];
        acc += a.x * b.x + a.y * b.y + a.z * b.z + a.w * b.w;
    }
    g_comb[r * FFH + j] = acc;
}

__global__ void rel2(const float* __restrict__ rel, const float* __restrict__ Wc,
                     const float* __restrict__ bc, const float* __restrict__ rng,
                     const float* __restrict__ rnb, float* __restrict__ outp) {
    int r = blockIdx.x;
    int o = threadIdx.x;   // 0..127
    const float4* cp = (const float4*)(g_comb + r * FFH);
    const float4* wp = (const float4*)(Wc + (size_t)o * FFH);
    float acc = bc[o];
#pragma unroll 8
    for (int i = 0; i < FFH / 4; i++) {
        float4 a = cp[i], b = wp[i];
        acc += a.x * b.x + a.y * b.y + a.z * b.z + a.w * b.w;
    }
    float val = rel[r * HH + o] + acc;
    // block LN over 128 values
    float s = val, q = val * val;
#pragma unroll
    for (int off = 16; off; off >>= 1) {
        s += __shfl_xor_sync(0xffffffffu, s, off);
        q += __shfl_xor_sync(0xffffffffu, q, off);
    }
    __shared__ float ssum[4], ssq[4];
    int w = o >> 5, lane = o & 31;
    if (lane == 0) { ssum[w] = s; ssq[w] = q; }
    __syncthreads();
    float tot = ssum[0] + ssum[1] + ssum[2] + ssum[3];
    float tsq = ssq[0] + ssq[1] + ssq[2] + ssq[3];
    float mu = tot * (1.0f / HH);
    float var = tsq * (1.0f / HH) - mu * mu;
    float inv = rsqrtf(var + 1e-5f);
    outp[r * HH + o] = (val - mu) * inv * rng[o] + rnb[o];
}

// ---------------- host ----------------
extern "C" void kernel_launch(void* const* d_in, const int* in_sizes, int n_in,
                              void* d_out, int out_size) {
    const float* node = (const float*)d_in[0];
    const float* qemb = (const float*)d_in[1];
    const int*   ei   = (const int*)d_in[2];
    const int*   et   = (const int*)d_in[3];
    const float* rel  = (const float*)d_in[4];
    const float* Wq   = (const float*)d_in[5];
    const float* bq   = (const float*)d_in[6];
    const float* Wk   = (const float*)d_in[7];
    const float* bk   = (const float*)d_in[8];
    const float* Wv   = (const float*)d_in[9];
    const float* bv   = (const float*)d_in[10];
    const float* Wo   = (const float*)d_in[11];
    const float* bo   = (const float*)d_in[12];
    const float* n1g  = (const float*)d_in[13];
    const float* n1b  = (const float*)d_in[14];
    const float* n2g  = (const float*)d_in[15];
    const float* n2b  = (const float*)d_in[16];
    const float* W1   = (const float*)d_in[17];
    const float* b1   = (const float*)d_in[18];
    const float* W2   = (const float*)d_in[19];
    const float* b2   = (const float*)d_in[20];
    const float* relW = (const float*)d_in[21];
    const float* relb = (const float*)d_in[22];
    const float* Wc   = (const float*)d_in[23];
    const float* bc   = (const float*)d_in[24];
    const float* rng  = (const float*)d_in[25];
    const float* rnb  = (const float*)d_in[26];
    float* out = (float*)d_out;

    float *p_q, *p_k, *p_v, *p_agg, *p_attn, *p_x1, *p_h1, *p_ffn, *p_bq, *p_bk;
    cudaGetSymbolAddress((void**)&p_q, g_q);
    cudaGetSymbolAddress((void**)&p_k, g_k);
    cudaGetSymbolAddress((void**)&p_v, g_v);
    cudaGetSymbolAddress((void**)&p_agg, g_agg);
    cudaGetSymbolAddress((void**)&p_attn, g_attn);
    cudaGetSymbolAddress((void**)&p_x1, g_x1);
    cudaGetSymbolAddress((void**)&p_h1, g_h1);
    cudaGetSymbolAddress((void**)&p_ffn, g_ffn);
    cudaGetSymbolAddress((void**)&p_bq, g_bq);
    cudaGetSymbolAddress((void**)&p_bk, g_bk);

    zero_kernel<<<(NN * HH + 255) / 256, 256>>>();
    prep_bias<<<1, 256>>>(qemb, Wq, Wk, bq, bk);

    dim3 gN(1, (NN + 127) / 128);
    gemm_bias<false><<<gN, 256>>>(node, Wq, p_bq, p_q, NN, HH, HH, 2 * HH);
    gemm_bias<false><<<gN, 256>>>(node, Wk, p_bk, p_k, NN, HH, HH, 2 * HH);
    gemm_bias<false><<<gN, 256>>>(node, Wv, bv, p_v, NN, HH, HH, HH);

    int eb = (EE * NHEADS + 255) / 256;
    edge_scores<<<eb, 256>>>(ei, et, rel);
    edge_agg<<<eb, 256>>>(ei);
    norm_agg<<<(NN * HH + 255) / 256, 256>>>();

    gemm_bias<false><<<gN, 256>>>(p_agg, Wo, bo, p_attn, NN, HH, HH, HH);
    ln_kernel<<<(NN + 7) / 8, 256>>>(node, p_attn, n1g, n1b, p_x1, NN);
    gemm_bias<true><<<dim3(4, (NN + 127) / 128), 256>>>(p_x1, W1, b1, p_h1, NN, FFH, HH, HH);
    gemm_bias<false><<<gN, 256>>>(p_h1, W2, b2, p_ffn, NN, HH, FFH, FFH);
    ln_kernel<<<(NN + 7) / 8, 256>>>(p_x1, p_ffn, n2g, n2b, out, NN);

    if (out_size >= NN * HH + RR * HH) {
        rel1<<<(RR * FFH + 255) / 256, 256>>>(rel, relW, relb);
        rel2<<<RR, 128>>>(rel, Wc, bc, rng, rnb, out + NN * HH);
    }
}

// round 6
// speedup vs baseline: 1.3162x; 1.3162x over previous
#include <cuda_runtime.h>
#include <stdint.h>
#include <math.h>

#define NN 50000
#define HH 128
#define NHEADS 8
#define HDIM 16
#define RR 100
#define EE 800000
#define FFH 512

// ---------------- scratch (static device globals; no allocation) ----------------
__device__ float g_q[NN * HH];
__device__ float g_k[NN * HH];
__device__ float g_v[NN * HH];
__device__ float g_scores[EE * NHEADS];
__device__ float g_segmax[NN * NHEADS];
__device__ float g_denom[NN * NHEADS];
__device__ float g_agg[NN * HH];
__device__ float g_attn[NN * HH];
__device__ float g_x1[NN * HH];
__device__ float g_h1[NN * FFH];
__device__ float g_ffn[NN * HH];
__device__ float g_bq[HH];
__device__ float g_bk[HH];
__device__ float g_comb[RR * FFH];

// ---------------- zero scratch that is atomically accumulated ----------------
__global__ void zero_kernel() {
    int i = blockIdx.x * blockDim.x + threadIdx.x;
    if (i < NN * HH) g_agg[i] = 0.0f;
    if (i < NN * NHEADS) { g_segmax[i] = 0.0f; g_denom[i] = 0.0f; }
}

// ---------------- fold query embedding into effective q/k biases ----------------
__global__ void prep_bias(const float* __restrict__ qemb,
                          const float* __restrict__ Wq, const float* __restrict__ Wk,
                          const float* __restrict__ bq, const float* __restrict__ bk) {
    int t = threadIdx.x;              // 0..255
    int o = t & 127;
    const float* Wrow = (t < 128 ? Wq : Wk) + o * (2 * HH) + HH;
    float acc = (t < 128 ? bq[o] : bk[o]);
#pragma unroll 4
    for (int j = 0; j < HH; j++) acc += qemb[j] * Wrow[j];
    if (t < 128) g_bq[o] = acc; else g_bk[o] = acc;
}

// ---------------- TF32 tensor-core GEMM ----------------
// C[M,Nout] = A[M,K] @ W.T + bias, W row-major [Nout, ldw]
// CTA tile 128x128, 8 warps (4x2), warp tile 32x64, k-chunk 32.
// Operands converted to tf32 (cvt.rna) at smem store; mma.sync.m16n8k8.

__device__ __forceinline__ uint32_t f2tf32(float x) {
    uint32_t u;
    asm("cvt.rna.tf32.f32 %0, %1;" : "=r"(u) : "f"(x));
    return u;
}

template <bool GELU>
__global__ __launch_bounds__(256) void gemm_tc(
    const float* __restrict__ A, const float* __restrict__ W,
    const float* __restrict__ bias, float* __restrict__ C,
    int M, int Nout, int K, int ldw)
{
    __shared__ uint32_t As[128][36];
    __shared__ uint32_t Bs[128][36];
    int tid = threadIdx.x;
    int warp = tid >> 5, lane = tid & 31;
    int wr = warp & 3;        // warp row (4 x 32 rows)
    int wc = warp >> 2;       // warp col (2 x 64 cols)
    int g = lane >> 2, tg = lane & 3;
    int row0 = blockIdx.y * 128, col0 = blockIdx.x * 128;

    float c[2][8][4];
#pragma unroll
    for (int mi = 0; mi < 2; mi++)
#pragma unroll
        for (int ni = 0; ni < 8; ni++)
#pragma unroll
            for (int j = 0; j < 4; j++) c[mi][ni][j] = 0.0f;

    for (int k0 = 0; k0 < K; k0 += 32) {
        // A tile: 128 rows x 32 k  (4 float4 per thread), cvt to tf32 at store
#pragma unroll
        for (int l = 0; l < 4; l++) {
            int i = tid + l * 256;       // float4 index 0..1023
            int r = i >> 3;
            int kq = i & 7;
            int grow = row0 + r;
            float4 v = make_float4(0.f, 0.f, 0.f, 0.f);
            if (grow < M)
                v = *(const float4*)(A + (size_t)grow * K + k0 + kq * 4);
            As[r][kq * 4 + 0] = f2tf32(v.x);
            As[r][kq * 4 + 1] = f2tf32(v.y);
            As[r][kq * 4 + 2] = f2tf32(v.z);
            As[r][kq * 4 + 3] = f2tf32(v.w);
        }
        // B tile: Bs[n][k] = W[(col0+n)*ldw + k0+k]
#pragma unroll
        for (int l = 0; l < 4; l++) {
            int i = tid + l * 256;
            int n = i >> 3;
            int kq = i & 7;
            float4 v = *(const float4*)(W + (size_t)(col0 + n) * ldw + k0 + kq * 4);
            Bs[n][kq * 4 + 0] = f2tf32(v.x);
            Bs[n][kq * 4 + 1] = f2tf32(v.y);
            Bs[n][kq * 4 + 2] = f2tf32(v.z);
            Bs[n][kq * 4 + 3] = f2tf32(v.w);
        }
        __syncthreads();
#pragma unroll
        for (int ks = 0; ks < 32; ks += 8) {
            uint32_t a[2][4];
#pragma unroll
            for (int mi = 0; mi < 2; mi++) {
                int rb = wr * 32 + mi * 16;
                a[mi][0] = As[rb + g][ks + tg];
                a[mi][1] = As[rb + g + 8][ks + tg];
                a[mi][2] = As[rb + g][ks + tg + 4];
                a[mi][3] = As[rb + g + 8][ks + tg + 4];
            }
#pragma unroll
            for (int ni = 0; ni < 8; ni++) {
                int nb = wc * 64 + ni * 8;
                uint32_t b0 = Bs[nb + g][ks + tg];
                uint32_t b1 = Bs[nb + g][ks + tg + 4];
#pragma unroll
                for (int mi = 0; mi < 2; mi++) {
                    asm volatile(
                        "mma.sync.aligned.m16n8k8.row.col.f32.tf32.tf32.f32 "
                        "{%0,%1,%2,%3}, {%4,%5,%6,%7}, {%8,%9}, {%0,%1,%2,%3};"
                        : "+f"(c[mi][ni][0]), "+f"(c[mi][ni][1]),
                          "+f"(c[mi][ni][2]), "+f"(c[mi][ni][3])
                        : "r"(a[mi][0]), "r"(a[mi][1]), "r"(a[mi][2]), "r"(a[mi][3]),
                          "r"(b0), "r"(b1));
                }
            }
        }
        __syncthreads();
    }

    // epilogue: bias (+ optional exact-erf GELU), float2 stores
#pragma unroll
    for (int mi = 0; mi < 2; mi++) {
        int r0g = row0 + wr * 32 + mi * 16 + g;
#pragma unroll
        for (int ni = 0; ni < 8; ni++) {
            int cb = col0 + wc * 64 + ni * 8 + tg * 2;
            float bv0 = bias[cb], bv1 = bias[cb + 1];
            float v0 = c[mi][ni][0] + bv0;
            float v1 = c[mi][ni][1] + bv1;
            float v2 = c[mi][ni][2] + bv0;
            float v3 = c[mi][ni][3] + bv1;
            if (GELU) {
                v0 = 0.5f * v0 * (1.0f + erff(v0 * 0.70710678118654752f));
                v1 = 0.5f * v1 * (1.0f + erff(v1 * 0.70710678118654752f));
                v2 = 0.5f * v2 * (1.0f + erff(v2 * 0.70710678118654752f));
                v3 = 0.5f * v3 * (1.0f + erff(v3 * 0.70710678118654752f));
            }
            if (r0g < M)
                *(float2*)(C + (size_t)r0g * Nout + cb) = make_float2(v0, v1);
            if (r0g + 8 < M)
                *(float2*)(C + (size_t)(r0g + 8) * Nout + cb) = make_float2(v2, v3);
        }
    }
}

// ---------------- edge pass A: scores + segment max ----------------
__global__ void edge_scores(const int* __restrict__ ei, const int* __restrict__ et,
                            const float* __restrict__ rel) {
    int idx = blockIdx.x * blockDim.x + threadIdx.x;
    if (idx >= EE * NHEADS) return;
    int e = idx >> 3, h = idx & 7;
    int s = ei[e];
    int d = ei[EE + e];
    int r = et[e];
    const float4* qp = (const float4*)(g_q + (size_t)d * HH + h * HDIM);
    const float4* kp = (const float4*)(g_k + (size_t)s * HH + h * HDIM);
    const float4* rp = (const float4*)(rel + (size_t)r * HH + h * HDIM);
    float acc = 0.0f;
#pragma unroll
    for (int i = 0; i < 4; i++) {
        float4 qv = qp[i], kv = kp[i], rv = rp[i];
        acc += qv.x * (kv.x + rv.x) + qv.y * (kv.y + rv.y)
             + qv.z * (kv.z + rv.z) + qv.w * (kv.w + rv.w);
    }
    float sc = acc * 0.25f;  // 1/sqrt(16)
    g_scores[idx] = sc;
    if (sc > 0.0f)
        atomicMax((int*)&g_segmax[d * NHEADS + h], __float_as_int(sc));
}

// ---------------- edge pass B: exp + weighted aggregation (unnormalized) ----------------
__global__ void edge_agg(const int* __restrict__ ei) {
    int idx = blockIdx.x * blockDim.x + threadIdx.x;
    if (idx >= EE * NHEADS) return;
    int e = idx >> 3, h = idx & 7;
    int s = ei[e];
    int d = ei[EE + e];
    float sc = g_scores[idx];
    float m = g_segmax[d * NHEADS + h];
    float ex = __expf(sc - m);
    atomicAdd(&g_denom[d * NHEADS + h], ex);
    const float4* vp = (const float4*)(g_v + (size_t)s * HH + h * HDIM);
    float* ap = g_agg + (size_t)d * HH + h * HDIM;
#pragma unroll
    for (int i = 0; i < 4; i++) {
        float4 vv = vp[i];
        asm volatile("red.global.add.v4.f32 [%0], {%1,%2,%3,%4};"
                     :: "l"(ap + i * 4),
                        "f"(ex * vv.x), "f"(ex * vv.y), "f"(ex * vv.z), "f"(ex * vv.w)
                     : "memory");
    }
}

// ---------------- normalize aggregated messages by denom ----------------
__global__ void norm_agg() {
    int i = blockIdx.x * blockDim.x + threadIdx.x;
    if (i >= NN * HH) return;
    int node = i >> 7;
    int h = (i >> 4) & 7;
    g_agg[i] = g_agg[i] / (g_denom[node * NHEADS + h] + 1e-8f);
}

// ---------------- layernorm(a + r) * g + b, warp per row ----------------
__global__ void ln_kernel(const float* __restrict__ a, const float* __restrict__ r,
                          const float* __restrict__ gam, const float* __restrict__ bet,
                          float* __restrict__ out, int M) {
    int warp = (blockIdx.x * blockDim.x + threadIdx.x) >> 5;
    int lane = threadIdx.x & 31;
    if (warp >= M) return;
    const float4* ap = (const float4*)(a + (size_t)warp * HH);
    const float4* rp = (const float4*)(r + (size_t)warp * HH);
    float4 va = ap[lane];
    float4 vr = rp[lane];
    float x0 = va.x + vr.x, x1 = va.y + vr.y, x2 = va.z + vr.z, x3 = va.w + vr.w;
    float s = x0 + x1 + x2 + x3;
    float q = x0 * x0 + x1 * x1 + x2 * x2 + x3 * x3;
#pragma unroll
    for (int off = 16; off; off >>= 1) {
        s += __shfl_xor_sync(0xffffffffu, s, off);
        q += __shfl_xor_sync(0xffffffffu, q, off);
    }
    float mu = s * (1.0f / HH);
    float var = q * (1.0f / HH) - mu * mu;
    float inv = rsqrtf(var + 1e-5f);
    float4 vg = ((const float4*)gam)[lane];
    float4 vb = ((const float4*)bet)[lane];
    float4 o;
    o.x = (x0 - mu) * inv * vg.x + vb.x;
    o.y = (x1 - mu) * inv * vg.y + vb.y;
    o.z = (x2 - mu) * inv * vg.z + vb.z;
    o.w = (x3 - mu) * inv * vg.w + vb.w;
    ((float4*)(out + (size_t)warp * HH))[lane] = o;
}

// ---------------- relational layer ----------------
__global__ void rel1(const float* __restrict__ rel, const float* __restrict__ relW,
                     const float* __restrict__ relb) {
    int idx = blockIdx.x * blockDim.x + threadIdx.x;   // < RR*FFH = 51200
    if (idx >= RR * FFH) return;
    int r = idx / FFH;
    int j = idx - r * FFH;
    int kk = j >> 7;
    int o = j & 127;
    const float4* rp = (const float4*)(rel + r * HH);
    const float4* wp = (const float4*)(relW + kk * HH * HH + o * HH);
    float acc = relb[j];
#pragma unroll 8
    for (int i = 0; i < 32; i++) {
        float4 a = rp[i], b = wp[i];
        acc += a.x * b.x + a.y * b.y + a.z * b.z + a.w * b.w;
    }
    g_comb[r * FFH + j] = acc;
}

__global__ void rel2(const float* __restrict__ rel, const float* __restrict__ Wc,
                     const float* __restrict__ bc, const float* __restrict__ rng,
                     const float* __restrict__ rnb, float* __restrict__ outp) {
    int r = blockIdx.x;
    int o = threadIdx.x;   // 0..127
    const float4* cp = (const float4*)(g_comb + r * FFH);
    const float4* wp = (const float4*)(Wc + (size_t)o * FFH);
    float acc = bc[o];
#pragma unroll 8
    for (int i = 0; i < FFH / 4; i++) {
        float4 a = cp[i], b = wp[i];
        acc += a.x * b.x + a.y * b.y + a.z * b.z + a.w * b.w;
    }
    float val = rel[r * HH + o] + acc;
    // block LN over 128 values
    float s = val, q = val * val;
#pragma unroll
    for (int off = 16; off; off >>= 1) {
        s += __shfl_xor_sync(0xffffffffu, s, off);
        q += __shfl_xor_sync(0xffffffffu, q, off);
    }
    __shared__ float ssum[4], ssq[4];
    int w = o >> 5, lane = o & 31;
    if (lane == 0) { ssum[w] = s; ssq[w] = q; }
    __syncthreads();
    float tot = ssum[0] + ssum[1] + ssum[2] + ssum[3];
    float tsq = ssq[0] + ssq[1] + ssq[2] + ssq[3];
    float mu = tot * (1.0f / HH);
    float var = tsq * (1.0f / HH) - mu * mu;
    float inv = rsqrtf(var + 1e-5f);
    outp[r * HH + o] = (val - mu) * inv * rng[o] + rnb[o];
}

// ---------------- host ----------------
extern "C" void kernel_launch(void* const* d_in, const int* in_sizes, int n_in,
                              void* d_out, int out_size) {
    const float* node = (const float*)d_in[0];
    const float* qemb = (const float*)d_in[1];
    const int*   ei   = (const int*)d_in[2];
    const int*   et   = (const int*)d_in[3];
    const float* rel  = (const float*)d_in[4];
    const float* Wq   = (const float*)d_in[5];
    const float* bq   = (const float*)d_in[6];
    const float* Wk   = (const float*)d_in[7];
    const float* bk   = (const float*)d_in[8];
    const float* Wv   = (const float*)d_in[9];
    const float* bv   = (const float*)d_in[10];
    const float* Wo   = (const float*)d_in[11];
    const float* bo   = (const float*)d_in[12];
    const float* n1g  = (const float*)d_in[13];
    const float* n1b  = (const float*)d_in[14];
    const float* n2g  = (const float*)d_in[15];
    const float* n2b  = (const float*)d_in[16];
    const float* W1   = (const float*)d_in[17];
    const float* b1   = (const float*)d_in[18];
    const float* W2   = (const float*)d_in[19];
    const float* b2   = (const float*)d_in[20];
    const float* relW = (const float*)d_in[21];
    const float* relb = (const float*)d_in[22];
    const float* Wc   = (const float*)d_in[23];
    const float* bc   = (const float*)d_in[24];
    const float* rng  = (const float*)d_in[25];
    const float* rnb  = (const float*)d_in[26];
    float* out = (float*)d_out;

    float *p_q, *p_k, *p_v, *p_agg, *p_attn, *p_x1, *p_h1, *p_ffn, *p_bq, *p_bk;
    cudaGetSymbolAddress((void**)&p_q, g_q);
    cudaGetSymbolAddress((void**)&p_k, g_k);
    cudaGetSymbolAddress((void**)&p_v, g_v);
    cudaGetSymbolAddress((void**)&p_agg, g_agg);
    cudaGetSymbolAddress((void**)&p_attn, g_attn);
    cudaGetSymbolAddress((void**)&p_x1, g_x1);
    cudaGetSymbolAddress((void**)&p_h1, g_h1);
    cudaGetSymbolAddress((void**)&p_ffn, g_ffn);
    cudaGetSymbolAddress((void**)&p_bq, g_bq);
    cudaGetSymbolAddress((void**)&p_bk, g_bk);

    zero_kernel<<<(NN * HH + 255) / 256, 256>>>();
    prep_bias<<<1, 256>>>(qemb, Wq, Wk, bq, bk);

    dim3 gN(1, (NN + 127) / 128);
    gemm_tc<false><<<gN, 256>>>(node, Wq, p_bq, p_q, NN, HH, HH, 2 * HH);
    gemm_tc<false><<<gN, 256>>>(node, Wk, p_bk, p_k, NN, HH, HH, 2 * HH);
    gemm_tc<false><<<gN, 256>>>(node, Wv, bv, p_v, NN, HH, HH, HH);

    int eb = (EE * NHEADS + 255) / 256;
    edge_scores<<<eb, 256>>>(ei, et, rel);
    edge_agg<<<eb, 256>>>(ei);
    norm_agg<<<(NN * HH + 255) / 256, 256>>>();

    gemm_tc<false><<<gN, 256>>>(p_agg, Wo, bo, p_attn, NN, HH, HH, HH);
    ln_kernel<<<(NN + 7) / 8, 256>>>(node, p_attn, n1g, n1b, p_x1, NN);
    gemm_tc<true><<<dim3(4, (NN + 127) / 128), 256>>>(p_x1, W1, b1, p_h1, NN, FFH, HH, HH);
    gemm_tc<false><<<gN, 256>>>(p_h1, W2, b2, p_ffn, NN, HH, FFH, FFH);
    ln_kernel<<<(NN + 7) / 8, 256>>>(p_x1, p_ffn, n2g, n2b, out, NN);

    if (out_size >= NN * HH + RR * HH) {
        rel1<<<(RR * FFH + 255) / 256, 256>>>(rel, relW, relb);
        rel2<<<RR, 128>>>(rel, Wc, bc, rng, rnb, out + NN * HH);
    }
}